// round 2
// baseline (speedup 1.0000x reference)
#include <cuda_runtime.h>
#include <cuda_bf16.h>
#include <math.h>

// Problem dims (fixed by dataset)
constexpr int BATCH = 8192;
constexpr int DIM   = 1024;
constexpr int NEXP  = 8;       // experts M
constexpr int HID   = 256;     // H
constexpr int KG    = NEXP * DIM;          // 8192 (GEMM1 K)
constexpr long long ED = (long long)BATCH * DIM; // expert stride in floats (8388608)

// GEMM1 tiling
#define BM 128
#define BN 128
#define BK 8
#define AS_STRIDE 132   // padded to kill STS bank conflicts

// Scratch: h = gelu(cat @ W1 + b1), [BATCH, HID] fp32 = 8 MB
__device__ float g_h[(size_t)BATCH * HID];

// ---------------- packed f32x2 helpers ----------------
__device__ __forceinline__ unsigned long long pk2(float lo, float hi) {
    unsigned long long r;
    asm("mov.b64 %0, {%1,%2};" : "=l"(r)
        : "r"(__float_as_uint(lo)), "r"(__float_as_uint(hi)));
    return r;
}
__device__ __forceinline__ void ffma2(unsigned long long &d,
                                      unsigned long long a,
                                      unsigned long long b) {
    asm("fma.rn.f32x2 %0, %1, %2, %0;" : "+l"(d) : "l"(a), "l"(b));
}
__device__ __forceinline__ float2 up2(unsigned long long v) {
    unsigned int a, b;
    asm("mov.b64 {%0,%1}, %2;" : "=r"(a), "=r"(b) : "l"(v));
    return make_float2(__uint_as_float(a), __uint_as_float(b));
}

__device__ __forceinline__ float gelu_exact(float x) {
    return 0.5f * x * (1.0f + erff(x * 0.70710678118654752f));
}

// ---------------- GEMM1 + bias + GELU ----------------
// C[b, n] = gelu( sum_k cat[b,k] * W1[k,n] + b1[n] )
// cat[b, k] = zs[k/1024][b][k%1024]
__global__ void __launch_bounds__(256, 1)
gemm1_gelu(const float* __restrict__ zs, const float* __restrict__ W1,
           const float* __restrict__ b1)
{
    __shared__ __align__(16) float As[2][BK][AS_STRIDE];
    __shared__ __align__(16) float Bs[2][BK][BN];

    const int tid  = threadIdx.x;
    const int brow = blockIdx.y * BM;
    const int bcol = blockIdx.x * BN;

    // A tile load mapping: 256 thr x float4 = 128 rows x 8 k
    const int a_row = tid >> 1;            // 0..127
    const int a_k   = (tid & 1) << 2;      // 0 or 4
    // B tile load mapping: 8 k x 128 cols
    const int b_k   = tid >> 5;            // 0..7
    const int b_col = (tid & 31) << 2;     // 0..124

    // compute mapping: rows {r0..r0+3, r0+64..r0+67}, cols {c0..c0+3, c0+64..c0+67}
    const int r0 = (tid >> 4) << 2;        // 0..60
    const int c0 = (tid & 15) << 2;        // 0..60

    const int arow_g = brow + a_row;

    unsigned long long acc[8][4];
    #pragma unroll
    for (int i = 0; i < 8; i++)
        #pragma unroll
        for (int j = 0; j < 4; j++) acc[i][j] = 0ull;

    const int NT = KG / BK;  // 1024

    float4 a_reg, b_reg;
    // prologue: tile 0
    {
        const int ka = a_k;  // kt = 0
        a_reg = *(const float4*)(zs + (((size_t)(ka >> 10)) << 23)
                                 + (size_t)arow_g * DIM + (ka & 1023));
        b_reg = *(const float4*)(W1 + (size_t)b_k * HID + bcol + b_col);
        As[0][a_k + 0][a_row] = a_reg.x;
        As[0][a_k + 1][a_row] = a_reg.y;
        As[0][a_k + 2][a_row] = a_reg.z;
        As[0][a_k + 3][a_row] = a_reg.w;
        *(float4*)&Bs[0][b_k][b_col] = b_reg;
    }
    __syncthreads();

    for (int kt = 0; kt < NT; kt++) {
        const int buf = kt & 1;
        if (kt + 1 < NT) {
            const int k  = (kt + 1) * BK;
            const int ka = k + a_k;
            a_reg = *(const float4*)(zs + (((size_t)(ka >> 10)) << 23)
                                     + (size_t)arow_g * DIM + (ka & 1023));
            b_reg = *(const float4*)(W1 + (size_t)(k + b_k) * HID + bcol + b_col);
        }
        #pragma unroll
        for (int kk = 0; kk < BK; kk++) {
            const float4 A0 = *(const float4*)&As[buf][kk][r0];
            const float4 A1 = *(const float4*)&As[buf][kk][r0 + 64];
            const float4 B0 = *(const float4*)&Bs[buf][kk][c0];
            const float4 B1 = *(const float4*)&Bs[buf][kk][c0 + 64];
            unsigned long long bp[4];
            bp[0] = pk2(B0.x, B0.y); bp[1] = pk2(B0.z, B0.w);
            bp[2] = pk2(B1.x, B1.y); bp[3] = pk2(B1.z, B1.w);
            const float a8[8] = {A0.x, A0.y, A0.z, A0.w, A1.x, A1.y, A1.z, A1.w};
            #pragma unroll
            for (int i = 0; i < 8; i++) {
                const unsigned long long ap2 = pk2(a8[i], a8[i]);
                #pragma unroll
                for (int jp = 0; jp < 4; jp++) ffma2(acc[i][jp], ap2, bp[jp]);
            }
        }
        if (kt + 1 < NT) {
            const int nb = buf ^ 1;
            As[nb][a_k + 0][a_row] = a_reg.x;
            As[nb][a_k + 1][a_row] = a_reg.y;
            As[nb][a_k + 2][a_row] = a_reg.z;
            As[nb][a_k + 3][a_row] = a_reg.w;
            *(float4*)&Bs[nb][b_k][b_col] = b_reg;
            __syncthreads();
        }
    }

    // epilogue: bias + GELU, write h
    const float4 bv0 = *(const float4*)(b1 + bcol + c0);
    const float4 bv1 = *(const float4*)(b1 + bcol + c0 + 64);
    #pragma unroll
    for (int i = 0; i < 8; i++) {
        const int grow = brow + r0 + ((i < 4) ? i : (64 + (i - 4)));
        const float2 p0 = up2(acc[i][0]);
        const float2 p1 = up2(acc[i][1]);
        const float2 p2 = up2(acc[i][2]);
        const float2 p3 = up2(acc[i][3]);
        float4 o0, o1;
        o0.x = gelu_exact(p0.x + bv0.x);
        o0.y = gelu_exact(p0.y + bv0.y);
        o0.z = gelu_exact(p1.x + bv0.z);
        o0.w = gelu_exact(p1.y + bv0.w);
        o1.x = gelu_exact(p2.x + bv1.x);
        o1.y = gelu_exact(p2.y + bv1.y);
        o1.z = gelu_exact(p3.x + bv1.z);
        o1.w = gelu_exact(p3.y + bv1.w);
        *(float4*)&g_h[(size_t)grow * HID + bcol + c0]      = o0;
        *(float4*)&g_h[(size_t)grow * HID + bcol + c0 + 64] = o1;
    }
}

// ---------------- gate (GEMM2 + top2 softmax) + combine ----------------
// one warp per batch row
__global__ void __launch_bounds__(256, 1)
gate_combine(const float* __restrict__ W2, const float* __restrict__ b2,
             const float* __restrict__ zs,
             float* __restrict__ fused, float* __restrict__ wout)
{
    const int warp = threadIdx.x >> 5;
    const int lane = threadIdx.x & 31;
    const int row  = blockIdx.x * 8 + warp;

    const float* hrow = g_h + (size_t)row * HID;
    float acc[8] = {0.f, 0.f, 0.f, 0.f, 0.f, 0.f, 0.f, 0.f};
    #pragma unroll
    for (int kk = 0; kk < 8; kk++) {
        const int k = kk * 32 + lane;
        const float hv = hrow[k];
        const float4 wa = *(const float4*)(W2 + (size_t)k * 8);
        const float4 wb = *(const float4*)(W2 + (size_t)k * 8 + 4);
        acc[0] += hv * wa.x; acc[1] += hv * wa.y;
        acc[2] += hv * wa.z; acc[3] += hv * wa.w;
        acc[4] += hv * wb.x; acc[5] += hv * wb.y;
        acc[6] += hv * wb.z; acc[7] += hv * wb.w;
    }
    #pragma unroll
    for (int m = 0; m < 8; m++) {
        #pragma unroll
        for (int s = 16; s > 0; s >>= 1)
            acc[m] += __shfl_xor_sync(0xffffffffu, acc[m], s);
        acc[m] += b2[m];
    }

    // top-2, jax tie-break (lower index wins on ties -> strict >)
    int i1 = 0; float l1 = acc[0];
    #pragma unroll
    for (int m = 1; m < 8; m++) if (acc[m] > l1) { l1 = acc[m]; i1 = m; }
    int i2 = (i1 == 0) ? 1 : 0; float l2 = acc[i2];
    #pragma unroll
    for (int m = 0; m < 8; m++)
        if (m != i1 && m != ((i1 == 0) ? 1 : 0) && acc[m] > l2) { l2 = acc[m]; i2 = m; }

    // softmax over (l1, l2), l1 >= l2
    const float e2  = expf(l2 - l1);
    const float inv = 1.0f / (1.0f + e2);
    const float w1  = inv;
    const float w2v = e2 * inv;

    if (lane < 8)
        wout[(size_t)row * 8 + lane] =
            (lane == i1) ? w1 : ((lane == i2) ? w2v : 0.0f);

    const float4* z1 = (const float4*)(zs + (size_t)i1 * ED + (size_t)row * DIM);
    const float4* z2 = (const float4*)(zs + (size_t)i2 * ED + (size_t)row * DIM);
    float4* fo = (float4*)(fused + (size_t)row * DIM);
    #pragma unroll
    for (int v = 0; v < 8; v++) {
        const int idx = v * 32 + lane;
        const float4 A  = z1[idx];
        const float4 Bv = z2[idx];
        float4 o;
        o.x = w1 * A.x + w2v * Bv.x;
        o.y = w1 * A.y + w2v * Bv.y;
        o.z = w1 * A.z + w2v * Bv.z;
        o.w = w1 * A.w + w2v * Bv.w;
        fo[idx] = o;
    }
}

extern "C" void kernel_launch(void* const* d_in, const int* in_sizes, int n_in,
                              void* d_out, int out_size)
{
    const float* zs = (const float*)d_in[0];
    const float* W1 = (const float*)d_in[1];
    const float* b1 = (const float*)d_in[2];
    const float* W2 = (const float*)d_in[3];
    const float* b2 = (const float*)d_in[4];

    float* out   = (float*)d_out;
    float* fused = out;                                   // [B, D]
    float* wout  = out + (size_t)BATCH * DIM;             // [B, M]

    gemm1_gelu<<<dim3(HID / BN, BATCH / BM), 256>>>(zs, W1, b1);
    gate_combine<<<BATCH / 8, 256>>>(W2, b2, zs, fused, wout);
}

// round 6
// speedup vs baseline: 1.0913x; 1.0913x over previous
#include <cuda_runtime.h>
#include <cuda_bf16.h>
#include <math.h>
#include <stdint.h>

// Problem dims (fixed by dataset)
constexpr int BATCH = 8192;
constexpr int DIM   = 1024;
constexpr int HID   = 256;
constexpr long long ED = (long long)BATCH * DIM;  // expert stride (floats)

// GEMM1 tiling (mma.sync m16n8k8 tf32, 3x emulation)
constexpr int BM = 128;
constexpr int BN = 128;
constexpr int BK = 32;
constexpr int NT = 8192 / BK;     // 256 k-tiles
constexpr int STAGES = 4;

constexpr int AST = 36;                      // A smem stride (floats): bank = 4m+k, conflict-free
constexpr int BST = 136;                     // B smem stride (floats): bank = 8k+n, conflict-free
constexpr int A_BYTES = BM * AST * 4;        // 18432
constexpr int B_BYTES = BK * BST * 4;        // 17408
constexpr int STAGE_BYTES = A_BYTES + B_BYTES;   // 35840
constexpr int SMEM_SZ = STAGES * STAGE_BYTES;    // 143360

// Scratch: h = gelu(cat @ W1 + b1), [BATCH, HID] fp32
__device__ float g_h[(size_t)BATCH * HID];

// ---------------- helpers ----------------
__device__ __forceinline__ void splt(float x, uint32_t& h, uint32_t& l) {
    asm("cvt.rna.tf32.f32 %0, %1;" : "=r"(h) : "f"(x));
    float r = x - __uint_as_float(h);
    asm("cvt.rna.tf32.f32 %0, %1;" : "=r"(l) : "f"(r));
}
__device__ __forceinline__ float gelu_exact(float x) {
    return 0.5f * x * (1.0f + erff(x * 0.70710678118654752f));
}
__device__ __forceinline__ void cpasync16(void* dst, const void* src) {
    uint32_t d;
    asm("{ .reg .u64 t; cvta.to.shared.u64 t, %1; cvt.u32.u64 %0, t; }"
        : "=r"(d) : "l"(dst));
    asm volatile("cp.async.cg.shared.global [%0], [%1], 16;"
                 :: "r"(d), "l"(src) : "memory");
}
__device__ __forceinline__ void mma_tf32(float* c, const uint32_t* a, const uint32_t* b) {
    asm volatile(
        "mma.sync.aligned.m16n8k8.row.col.f32.tf32.tf32.f32 "
        "{%0,%1,%2,%3}, {%4,%5,%6,%7}, {%8,%9}, {%0,%1,%2,%3};"
        : "+f"(c[0]), "+f"(c[1]), "+f"(c[2]), "+f"(c[3])
        : "r"(a[0]), "r"(a[1]), "r"(a[2]), "r"(a[3]), "r"(b[0]), "r"(b[1]));
}

// ---------------- GEMM1: 3xTF32 mma.sync + bias + GELU ----------------
// h[b, n] = gelu( sum_k cat[b,k] * W1[k,n] + b1[n] ),  cat[b,k] = zs[k>>10][b][k&1023]
__global__ void __launch_bounds__(256, 1)
gemm1_mma(const float* __restrict__ zs, const float* __restrict__ W1,
          const float* __restrict__ b1)
{
    extern __shared__ float smem[];
    const int tid  = threadIdx.x;
    const int lane = tid & 31;
    const int wid  = tid >> 5;
    const int wm   = wid & 1;          // 2 warps along M (64 each)
    const int wn   = wid >> 1;         // 4 warps along N (32 each)
    const int brow = blockIdx.y * BM;
    const int bcol = blockIdx.x * BN;

    // copy one stage's tiles for k-tile kt into stage buffer s
    auto copy_tile = [&](int kt, int s) {
        float* As = smem + (size_t)s * (STAGE_BYTES / 4);
        float* Bs = As + A_BYTES / 4;
        const int k0 = kt * BK;
        const int e  = k0 >> 10;                    // expert block (BK | 1024)
        const float* abase = zs + (size_t)e * ED + (k0 & 1023);
        #pragma unroll
        for (int i = 0; i < 4; i++) {
            const int c  = tid + i * 256;           // A: 1024 16B-chunks
            const int r  = c >> 3;
            const int kc = c & 7;
            cpasync16(As + r * AST + kc * 4,
                      abase + (size_t)(brow + r) * DIM + kc * 4);
        }
        #pragma unroll
        for (int i = 0; i < 4; i++) {
            const int c  = tid + i * 256;           // B: 1024 16B-chunks
            const int r  = c >> 5;
            const int nc = c & 31;
            cpasync16(Bs + r * BST + nc * 4,
                      W1 + (size_t)(k0 + r) * HID + bcol + nc * 4);
        }
        asm volatile("cp.async.commit_group;" ::: "memory");
    };

    float acc[4][4][4];
    #pragma unroll
    for (int i = 0; i < 4; i++)
        #pragma unroll
        for (int j = 0; j < 4; j++)
            #pragma unroll
            for (int q = 0; q < 4; q++) acc[i][j][q] = 0.0f;

    // prologue: stages 0..S-2
    #pragma unroll
    for (int s = 0; s < STAGES - 1; s++) copy_tile(s, s);

    const int l4  = lane & 3;
    const int ld4 = lane >> 2;

    for (int kt = 0; kt < NT; kt++) {
        asm volatile("cp.async.wait_group %0;" :: "n"(STAGES - 2) : "memory");
        __syncthreads();
        // prefetch next stage into the buffer freed by iteration kt-1
        if (kt + STAGES - 1 < NT)
            copy_tile(kt + STAGES - 1, (kt + STAGES - 1) % STAGES);
        else
            asm volatile("cp.async.commit_group;" ::: "memory");

        const float* As = smem + (size_t)(kt % STAGES) * (STAGE_BYTES / 4);
        const float* Bs = As + A_BYTES / 4;

        #pragma unroll
        for (int k8 = 0; k8 < BK; k8 += 8) {
            // B fragments: 4 n-tiles, split hi/lo
            uint32_t bh[4][2], bl[4][2];
            #pragma unroll
            for (int nt = 0; nt < 4; nt++) {
                const int n = wn * 32 + nt * 8 + ld4;
                float f0 = Bs[(k8 + l4)     * BST + n];
                float f1 = Bs[(k8 + l4 + 4) * BST + n];
                splt(f0, bh[nt][0], bl[nt][0]);
                splt(f1, bh[nt][1], bl[nt][1]);
            }
            #pragma unroll
            for (int mt = 0; mt < 4; mt++) {
                const int m = wm * 64 + mt * 16 + ld4;
                uint32_t ah[4], al[4];
                float f0 = As[m       * AST + k8 + l4];
                float f1 = As[(m + 8) * AST + k8 + l4];
                float f2 = As[m       * AST + k8 + l4 + 4];
                float f3 = As[(m + 8) * AST + k8 + l4 + 4];
                splt(f0, ah[0], al[0]);
                splt(f1, ah[1], al[1]);
                splt(f2, ah[2], al[2]);
                splt(f3, ah[3], al[3]);
                #pragma unroll
                for (int nt = 0; nt < 4; nt++) {
                    mma_tf32(acc[mt][nt], ah, bh[nt]);
                    mma_tf32(acc[mt][nt], ah, bl[nt]);
                    mma_tf32(acc[mt][nt], al, bh[nt]);
                }
            }
        }
    }

    // epilogue: bias + exact GELU, direct STG (float2 per half-fragment)
    #pragma unroll
    for (int mt = 0; mt < 4; mt++) {
        const int r0 = brow + wm * 64 + mt * 16 + ld4;
        #pragma unroll
        for (int nt = 0; nt < 4; nt++) {
            const int cg = bcol + wn * 32 + nt * 8 + 2 * l4;
            const float bx = b1[cg], by = b1[cg + 1];
            float2 o0, o1;
            o0.x = gelu_exact(acc[mt][nt][0] + bx);
            o0.y = gelu_exact(acc[mt][nt][1] + by);
            o1.x = gelu_exact(acc[mt][nt][2] + bx);
            o1.y = gelu_exact(acc[mt][nt][3] + by);
            *(float2*)(g_h + (size_t)r0 * HID + cg)       = o0;
            *(float2*)(g_h + (size_t)(r0 + 8) * HID + cg) = o1;
        }
    }
}

// ---------------- gate (GEMM2 + top2 softmax) + combine ----------------
__global__ void __launch_bounds__(256, 1)
gate_combine(const float* __restrict__ W2, const float* __restrict__ b2,
             const float* __restrict__ zs,
             float* __restrict__ fused, float* __restrict__ wout)
{
    const int warp = threadIdx.x >> 5;
    const int lane = threadIdx.x & 31;
    const int row  = blockIdx.x * 8 + warp;

    const float* hrow = g_h + (size_t)row * HID;
    float acc[8] = {0.f, 0.f, 0.f, 0.f, 0.f, 0.f, 0.f, 0.f};
    #pragma unroll
    for (int kk = 0; kk < 8; kk++) {
        const int k = kk * 32 + lane;
        const float hv = hrow[k];
        const float4 wa = *(const float4*)(W2 + (size_t)k * 8);
        const float4 wb = *(const float4*)(W2 + (size_t)k * 8 + 4);
        acc[0] += hv * wa.x; acc[1] += hv * wa.y;
        acc[2] += hv * wa.z; acc[3] += hv * wa.w;
        acc[4] += hv * wb.x; acc[5] += hv * wb.y;
        acc[6] += hv * wb.z; acc[7] += hv * wb.w;
    }
    #pragma unroll
    for (int m = 0; m < 8; m++) {
        #pragma unroll
        for (int s = 16; s > 0; s >>= 1)
            acc[m] += __shfl_xor_sync(0xffffffffu, acc[m], s);
        acc[m] += b2[m];
    }

    // top-2, jax tie-break (lower index wins -> strict >)
    int i1 = 0; float l1 = acc[0];
    #pragma unroll
    for (int m = 1; m < 8; m++) if (acc[m] > l1) { l1 = acc[m]; i1 = m; }
    int i2 = (i1 == 0) ? 1 : 0; float l2 = acc[i2];
    #pragma unroll
    for (int m = 0; m < 8; m++)
        if (m != i1 && m != ((i1 == 0) ? 1 : 0) && acc[m] > l2) { l2 = acc[m]; i2 = m; }

    const float e2  = expf(l2 - l1);
    const float inv = 1.0f / (1.0f + e2);
    const float w1  = inv;
    const float w2v = e2 * inv;

    if (lane < 8)
        wout[(size_t)row * 8 + lane] =
            (lane == i1) ? w1 : ((lane == i2) ? w2v : 0.0f);

    const float4* z1 = (const float4*)(zs + (size_t)i1 * ED + (size_t)row * DIM);
    const float4* z2 = (const float4*)(zs + (size_t)i2 * ED + (size_t)row * DIM);
    float4* fo = (float4*)(fused + (size_t)row * DIM);
    #pragma unroll
    for (int v = 0; v < 8; v++) {
        const int idx = v * 32 + lane;
        const float4 A  = z1[idx];
        const float4 Bv = z2[idx];
        float4 o;
        o.x = w1 * A.x + w2v * Bv.x;
        o.y = w1 * A.y + w2v * Bv.y;
        o.z = w1 * A.z + w2v * Bv.z;
        o.w = w1 * A.w + w2v * Bv.w;
        fo[idx] = o;
    }
}

extern "C" void kernel_launch(void* const* d_in, const int* in_sizes, int n_in,
                              void* d_out, int out_size)
{
    const float* zs = (const float*)d_in[0];
    const float* W1 = (const float*)d_in[1];
    const float* b1 = (const float*)d_in[2];
    const float* W2 = (const float*)d_in[3];
    const float* b2 = (const float*)d_in[4];

    float* out   = (float*)d_out;
    float* fused = out;                        // [B, D]
    float* wout  = out + (size_t)BATCH * DIM;  // [B, M]

    cudaFuncSetAttribute(gemm1_mma, cudaFuncAttributeMaxDynamicSharedMemorySize, SMEM_SZ);

    gemm1_mma<<<dim3(BN == 128 ? HID / BN : 2, BATCH / BM), 256, SMEM_SZ>>>(zs, W1, b1);
    gate_combine<<<BATCH / 8, 256>>>(W2, b2, zs, fused, wout);
}